// round 1
// baseline (speedup 1.0000x reference)
#include <cuda_runtime.h>

// Problem constants (fixed shapes from the reference setup_inputs).
#define NREF  4096
#define NIN   8192
#define DFEAT 512
#define PDIM  256

// Scratch for the masked kernel matrix K [NREF, NIN] (128 MB).
// __device__ global: allowed under the allocation guards.
__device__ float g_K[(size_t)NREF * (size_t)NIN];

// ---------------------------------------------------------------------------
// GEMM1: K[i,j] = mask(Z_ref[i]==Z[j]) * (X_ref[i] . desc[j])^expK
// C = X (4096x512) * desc^T (512x8192), tiled 128x128x16, 8x8 per thread.
// ---------------------------------------------------------------------------
__global__ __launch_bounds__(256) void gemm1_pow_mask_kernel(
    const float* __restrict__ X,     // [NREF, DFEAT]
    const float* __restrict__ Dsc,   // [NIN, DFEAT]
    const int*   __restrict__ Zr,    // [NREF]
    const int*   __restrict__ Zq,    // [NIN]
    const int*   __restrict__ expKp) // [1]
{
    __shared__ float As[16][128];   // As[k][m]
    __shared__ float Bs[16][128];   // Bs[k][n]

    const int tid   = threadIdx.x;
    const int iBase = blockIdx.y * 128;
    const int jBase = blockIdx.x * 128;

    const int ty = tid >> 4;          // 0..15
    const int tx = tid & 15;          // 0..15

    // Loader mapping: 128 rows x 16 k = 512 float4; 2 per thread.
    const int lrow = tid >> 2;        // 0..63
    const int lk4  = (tid & 3) << 2;  // 0,4,8,12

    float acc[8][8];
    #pragma unroll
    for (int m = 0; m < 8; m++)
        #pragma unroll
        for (int n = 0; n < 8; n++) acc[m][n] = 0.0f;

    for (int kt = 0; kt < DFEAT; kt += 16) {
        // Load A tile (X rows), transposed into As[k][m]
        #pragma unroll
        for (int r = 0; r < 2; r++) {
            const int row = lrow + r * 64;
            float4 av = *(const float4*)(X + (size_t)(iBase + row) * DFEAT + kt + lk4);
            As[lk4 + 0][row] = av.x;
            As[lk4 + 1][row] = av.y;
            As[lk4 + 2][row] = av.z;
            As[lk4 + 3][row] = av.w;
        }
        // Load B tile (desc rows), transposed into Bs[k][n]
        #pragma unroll
        for (int r = 0; r < 2; r++) {
            const int row = lrow + r * 64;
            float4 bv = *(const float4*)(Dsc + (size_t)(jBase + row) * DFEAT + kt + lk4);
            Bs[lk4 + 0][row] = bv.x;
            Bs[lk4 + 1][row] = bv.y;
            Bs[lk4 + 2][row] = bv.z;
            Bs[lk4 + 3][row] = bv.w;
        }
        __syncthreads();

        #pragma unroll
        for (int k = 0; k < 16; k++) {
            float ar[8], br[8];
            float4 a0 = *(const float4*)(&As[k][ty * 8]);
            float4 a1 = *(const float4*)(&As[k][ty * 8 + 4]);
            float4 b0 = *(const float4*)(&Bs[k][tx * 8]);
            float4 b1 = *(const float4*)(&Bs[k][tx * 8 + 4]);
            ar[0]=a0.x; ar[1]=a0.y; ar[2]=a0.z; ar[3]=a0.w;
            ar[4]=a1.x; ar[5]=a1.y; ar[6]=a1.z; ar[7]=a1.w;
            br[0]=b0.x; br[1]=b0.y; br[2]=b0.z; br[3]=b0.w;
            br[4]=b1.x; br[5]=b1.y; br[6]=b1.z; br[7]=b1.w;
            #pragma unroll
            for (int m = 0; m < 8; m++)
                #pragma unroll
                for (int n = 0; n < 8; n++)
                    acc[m][n] = fmaf(ar[m], br[n], acc[m][n]);
        }
        __syncthreads();
    }

    // Epilogue: v^expK, masked by element match, store to scratch.
    const int e = *expKp;
    int zi[8], zj[8];
    #pragma unroll
    for (int m = 0; m < 8; m++) zi[m] = Zr[iBase + ty * 8 + m];
    #pragma unroll
    for (int n = 0; n < 8; n++) zj[n] = Zq[jBase + tx * 8 + n];

    #pragma unroll
    for (int m = 0; m < 8; m++) {
        const size_t rowOff = (size_t)(iBase + ty * 8 + m) * NIN + jBase + tx * 8;
        #pragma unroll
        for (int n = 0; n < 8; n++) {
            float v = acc[m][n];
            float p = 1.0f;
            for (int t = 0; t < e; t++) p *= v;   // v^expK (expK small)
            g_K[rowOff + n] = (zi[m] == zj[n]) ? p : 0.0f;
        }
    }
}

// ---------------------------------------------------------------------------
// GEMM2: y = Alpha (256x4096) * K_masked (4096x8192)
// Tiled 128x128x16, 8x8 per thread. Grid (64, 2).
// ---------------------------------------------------------------------------
__global__ __launch_bounds__(256) void gemm2_kernel(
    const float* __restrict__ A,     // Alpha [PDIM, NREF]
    float* __restrict__ Y)           // [PDIM, NIN]
{
    __shared__ float As[16][128];    // As[k][m]
    __shared__ float Bs[16][128];    // Bs[k][n]

    const int tid   = threadIdx.x;
    const int mBase = blockIdx.y * 128;
    const int nBase = blockIdx.x * 128;

    const int ty = tid >> 4;
    const int tx = tid & 15;

    // A loader: 128 rows x 16 k
    const int lrow = tid >> 2;
    const int lk4  = (tid & 3) << 2;
    // B loader: 16 k-rows x 128 n
    const int bkrow = tid >> 5;          // 0..7
    const int bn4   = (tid & 31) << 2;   // 0..124

    float acc[8][8];
    #pragma unroll
    for (int m = 0; m < 8; m++)
        #pragma unroll
        for (int n = 0; n < 8; n++) acc[m][n] = 0.0f;

    for (int kt = 0; kt < NREF; kt += 16) {
        #pragma unroll
        for (int r = 0; r < 2; r++) {
            const int row = lrow + r * 64;
            float4 av = *(const float4*)(A + (size_t)(mBase + row) * NREF + kt + lk4);
            As[lk4 + 0][row] = av.x;
            As[lk4 + 1][row] = av.y;
            As[lk4 + 2][row] = av.z;
            As[lk4 + 3][row] = av.w;
        }
        #pragma unroll
        for (int r = 0; r < 2; r++) {
            const int k = bkrow + r * 8;
            float4 bv = *(const float4*)(g_K + (size_t)(kt + k) * NIN + nBase + bn4);
            *(float4*)(&Bs[k][bn4]) = bv;
        }
        __syncthreads();

        #pragma unroll
        for (int k = 0; k < 16; k++) {
            float ar[8], br[8];
            float4 a0 = *(const float4*)(&As[k][ty * 8]);
            float4 a1 = *(const float4*)(&As[k][ty * 8 + 4]);
            float4 b0 = *(const float4*)(&Bs[k][tx * 8]);
            float4 b1 = *(const float4*)(&Bs[k][tx * 8 + 4]);
            ar[0]=a0.x; ar[1]=a0.y; ar[2]=a0.z; ar[3]=a0.w;
            ar[4]=a1.x; ar[5]=a1.y; ar[6]=a1.z; ar[7]=a1.w;
            br[0]=b0.x; br[1]=b0.y; br[2]=b0.z; br[3]=b0.w;
            br[4]=b1.x; br[5]=b1.y; br[6]=b1.z; br[7]=b1.w;
            #pragma unroll
            for (int m = 0; m < 8; m++)
                #pragma unroll
                for (int n = 0; n < 8; n++)
                    acc[m][n] = fmaf(ar[m], br[n], acc[m][n]);
        }
        __syncthreads();
    }

    #pragma unroll
    for (int m = 0; m < 8; m++) {
        const size_t rowOff = (size_t)(mBase + ty * 8 + m) * NIN + nBase + tx * 8;
        float4 o0, o1;
        o0.x = acc[m][0]; o0.y = acc[m][1]; o0.z = acc[m][2]; o0.w = acc[m][3];
        o1.x = acc[m][4]; o1.y = acc[m][5]; o1.z = acc[m][6]; o1.w = acc[m][7];
        *(float4*)(Y + rowOff)     = o0;
        *(float4*)(Y + rowOff + 4) = o1;
    }
}

extern "C" void kernel_launch(void* const* d_in, const int* in_sizes, int n_in,
                              void* d_out, int out_size) {
    const float* Alpha = (const float*)d_in[0];   // [256, 4096]
    const float* X_ref = (const float*)d_in[1];   // [4096, 512]
    const float* desc  = (const float*)d_in[2];   // [8192, 512]
    const int*   Z_ref = (const int*)d_in[3];     // [4096]
    const int*   Z     = (const int*)d_in[4];     // [8192]
    const int*   expK  = (const int*)d_in[5];     // [1]
    float* Y = (float*)d_out;                     // [256, 8192]

    dim3 g1(NIN / 128, NREF / 128);   // 64 x 32
    gemm1_pow_mask_kernel<<<g1, 256>>>(X_ref, desc, Z_ref, Z, expK);

    dim3 g2(NIN / 128, PDIM / 128);   // 64 x 2
    gemm2_kernel<<<g2, 256>>>(Alpha, Y);
}

// round 3
// speedup vs baseline: 1.9328x; 1.9328x over previous
#include <cuda_runtime.h>
#include <cuda_bf16.h>

#define NREF  4096
#define NIN   8192
#define DFEAT 512
#define PDIM  256
#define LDS   40          // 32 + 8 pad (bf16 elems) -> 80B row stride, conflict-free ldmatrix

// ---------------- scratch (device globals: allocation-guard safe) ----------
__device__ __nv_bfloat16 g_Xh[NREF * DFEAT];
__device__ __nv_bfloat16 g_Xl[NREF * DFEAT];
__device__ __nv_bfloat16 g_Dh[NIN * DFEAT];
__device__ __nv_bfloat16 g_Dl[NIN * DFEAT];
__device__ __nv_bfloat16 g_Ah[PDIM * NREF];
__device__ __nv_bfloat16 g_Al[PDIM * NREF];
__device__ __nv_bfloat16 g_Kth[(size_t)NIN * NREF];   // K^T hi  [NIN, NREF]
__device__ __nv_bfloat16 g_Ktl[(size_t)NIN * NREF];   // K^T lo

struct __align__(16) SmemT {
    __nv_bfloat16 A[2][128 * LDS];
    __nv_bfloat16 B[2][128 * LDS];
    int Zcol[128];
};

__device__ __forceinline__ unsigned sm32(const void* p) {
    unsigned r;
    asm("{.reg .u64 t; cvta.to.shared.u64 t, %1; cvt.u32.u64 %0, t;}" : "=r"(r) : "l"(p));
    return r;
}

// Load one 128x32 bf16 tile (row-major source, row stride K elems) via cp.async.
__device__ __forceinline__ void load_tile(unsigned sbuf, const __nv_bfloat16* src,
                                          int rowBase, int K, int kOff, int tid) {
    const int row = tid >> 1;
    const char* g = (const char*)(src + (size_t)(rowBase + row) * K + kOff + (tid & 1) * 16);
    const unsigned s = sbuf + row * (LDS * 2) + (tid & 1) * 32;
    asm volatile("cp.async.cg.shared.global [%0], [%1], 16;\n\t"
                 "cp.async.cg.shared.global [%2], [%3], 16;"
                 :: "r"(s), "l"(g), "r"(s + 16), "l"(g + 16));
}

__device__ __forceinline__ void mma16(float* c, const unsigned* a, unsigned b0, unsigned b1) {
    asm volatile(
        "mma.sync.aligned.m16n8k16.row.col.f32.bf16.bf16.f32 "
        "{%0,%1,%2,%3}, {%4,%5,%6,%7}, {%8,%9}, {%0,%1,%2,%3};"
        : "+f"(c[0]), "+f"(c[1]), "+f"(c[2]), "+f"(c[3])
        : "r"(a[0]), "r"(a[1]), "r"(a[2]), "r"(a[3]), "r"(b0), "r"(b1));
}

// One BLK_K=32 step: warp computes its 32x64 tile (2 m-tiles x 8 n-tiles).
__device__ __forceinline__ void compute_k32(unsigned sA, unsigned sB,
                                            int warpM, int warpN, int lane,
                                            float (*c)[8][4]) {
#pragma unroll
    for (int kk = 0; kk < 32; kk += 16) {
        unsigned a[2][4], b[4][4];
#pragma unroll
        for (int mi = 0; mi < 2; mi++) {
            unsigned addr = sA + ((warpM * 32 + mi * 16 + (lane & 15)) * LDS
                                  + kk + (lane >> 4) * 8) * 2;
            asm volatile("ldmatrix.sync.aligned.m8n8.x4.shared.b16 {%0,%1,%2,%3}, [%4];"
                         : "=r"(a[mi][0]), "=r"(a[mi][1]), "=r"(a[mi][2]), "=r"(a[mi][3])
                         : "r"(addr));
        }
#pragma unroll
        for (int g = 0; g < 4; g++) {
            unsigned addr = sB + ((warpN * 64 + g * 16 + (lane & 7) + ((lane >> 4) & 1) * 8) * LDS
                                  + kk + ((lane >> 3) & 1) * 8) * 2;
            asm volatile("ldmatrix.sync.aligned.m8n8.x4.shared.b16 {%0,%1,%2,%3}, [%4];"
                         : "=r"(b[g][0]), "=r"(b[g][1]), "=r"(b[g][2]), "=r"(b[g][3])
                         : "r"(addr));
        }
#pragma unroll
        for (int mi = 0; mi < 2; mi++)
#pragma unroll
            for (int ni = 0; ni < 8; ni++)
                mma16(c[mi][ni], a[mi], b[ni >> 1][(ni & 1) * 2], b[ni >> 1][(ni & 1) * 2 + 1]);
    }
}

// ---------------------------------------------------------------------------
// GEMM1 (transposed): Kt[j,i] = mask(Z[j]==Z_ref[i]) * (desc[j].X_ref[i])^expK
// K-split segments: Dh.Xh + Dh.Xl + Dl.Xh  (48 iters of K=32)
// ---------------------------------------------------------------------------
__global__ __launch_bounds__(256, 2) void gemm1_mma(const int* __restrict__ Zq,
                                                    const int* __restrict__ Zx,
                                                    const int* __restrict__ expKp) {
    __shared__ SmemT sm;
    const int tid = threadIdx.x, lane = tid & 31, wid = tid >> 5;
    const int warpM = wid & 3, warpN = wid >> 2;
    const int jBase = blockIdx.y * 128, iBase = blockIdx.x * 128;
    if (tid < 128) sm.Zcol[tid] = Zx[iBase + tid];

    float c[2][8][4];
#pragma unroll
    for (int i = 0; i < 2; i++)
#pragma unroll
        for (int j = 0; j < 8; j++)
#pragma unroll
            for (int k = 0; k < 4; k++) c[i][j][k] = 0.0f;

    const unsigned sA[2] = {sm32(sm.A[0]), sm32(sm.A[1])};
    const unsigned sB[2] = {sm32(sm.B[0]), sm32(sm.B[1])};

    load_tile(sA[0], g_Dh, jBase, DFEAT, 0, tid);
    load_tile(sB[0], g_Xh, iBase, DFEAT, 0, tid);
    asm volatile("cp.async.commit_group;" ::: "memory");

    const int NITER = 48;               // 3 segments x 512/32
    for (int it = 0; it < NITER; it++) {
        const int b = it & 1;
        if (it + 1 < NITER) {
            const int n = it + 1, seg = n >> 4, kOff = (n & 15) * 32;
            const __nv_bfloat16 *pa, *pb;
            if (seg == 0)      { pa = g_Dh; pb = g_Xh; }
            else if (seg == 1) { pa = g_Dh; pb = g_Xl; }
            else               { pa = g_Dl; pb = g_Xh; }
            load_tile(sA[1 - b], pa, jBase, DFEAT, kOff, tid);
            load_tile(sB[1 - b], pb, iBase, DFEAT, kOff, tid);
            asm volatile("cp.async.commit_group;" ::: "memory");
            asm volatile("cp.async.wait_group 1;" ::: "memory");
        } else {
            asm volatile("cp.async.wait_group 0;" ::: "memory");
        }
        __syncthreads();
        compute_k32(sA[b], sB[b], warpM, warpN, lane, c);
        __syncthreads();
    }

    // epilogue: pow, mask, bf16 hi/lo split, store K^T
    const int e = expKp[0];
#pragma unroll
    for (int mi = 0; mi < 2; mi++) {
        const int r0 = jBase + warpM * 32 + mi * 16 + (lane >> 2);
        const int zr0 = Zq[r0], zr1 = Zq[r0 + 8];
        const size_t ro0 = (size_t)r0 * NREF, ro1 = (size_t)(r0 + 8) * NREF;
#pragma unroll
        for (int ni = 0; ni < 8; ni++) {
            const int colL = warpN * 64 + ni * 8 + 2 * (lane & 3);
            const int zc0 = sm.Zcol[colL], zc1 = sm.Zcol[colL + 1];
            float v0 = c[mi][ni][0], v1 = c[mi][ni][1];
            float v2 = c[mi][ni][2], v3 = c[mi][ni][3];
            float p0 = 1.f, p1 = 1.f, p2 = 1.f, p3 = 1.f;
            for (int t = 0; t < e; t++) { p0 *= v0; p1 *= v1; p2 *= v2; p3 *= v3; }
            if (zr0 != zc0) p0 = 0.f;
            if (zr0 != zc1) p1 = 0.f;
            if (zr1 != zc0) p2 = 0.f;
            if (zr1 != zc1) p3 = 0.f;

            __nv_bfloat16 h0 = __float2bfloat16(p0), h1 = __float2bfloat16(p1);
            __nv_bfloat16 h2 = __float2bfloat16(p2), h3 = __float2bfloat16(p3);
            __nv_bfloat162 hh01, hh23, ll01, ll23;
            hh01.x = h0; hh01.y = h1;
            hh23.x = h2; hh23.y = h3;
            ll01.x = __float2bfloat16(p0 - __bfloat162float(h0));
            ll01.y = __float2bfloat16(p1 - __bfloat162float(h1));
            ll23.x = __float2bfloat16(p2 - __bfloat162float(h2));
            ll23.y = __float2bfloat16(p3 - __bfloat162float(h3));

            const size_t cg = (size_t)iBase + colL;
            *(__nv_bfloat162*)(g_Kth + ro0 + cg) = hh01;
            *(__nv_bfloat162*)(g_Kth + ro1 + cg) = hh23;
            *(__nv_bfloat162*)(g_Ktl + ro0 + cg) = ll01;
            *(__nv_bfloat162*)(g_Ktl + ro1 + cg) = ll23;
        }
    }
}

// ---------------------------------------------------------------------------
// GEMM2: Y[p,j] = Alpha[p] . Kt[j]   segments: Ah.Kh + Al.Kh + Ah.Kl
// ---------------------------------------------------------------------------
__global__ __launch_bounds__(256, 2) void gemm2_mma(float* __restrict__ Y) {
    __shared__ SmemT sm;
    const int tid = threadIdx.x, lane = tid & 31, wid = tid >> 5;
    const int warpM = wid & 3, warpN = wid >> 2;
    const int pBase = blockIdx.y * 128, jBase = blockIdx.x * 128;

    float c[2][8][4];
#pragma unroll
    for (int i = 0; i < 2; i++)
#pragma unroll
        for (int j = 0; j < 8; j++)
#pragma unroll
            for (int k = 0; k < 4; k++) c[i][j][k] = 0.0f;

    const unsigned sA[2] = {sm32(sm.A[0]), sm32(sm.A[1])};
    const unsigned sB[2] = {sm32(sm.B[0]), sm32(sm.B[1])};

    load_tile(sA[0], g_Ah, pBase, NREF, 0, tid);
    load_tile(sB[0], g_Kth, jBase, NREF, 0, tid);
    asm volatile("cp.async.commit_group;" ::: "memory");

    const int NITER = 384;              // 3 segments x 4096/32
    for (int it = 0; it < NITER; it++) {
        const int b = it & 1;
        if (it + 1 < NITER) {
            const int n = it + 1, seg = n >> 7, kOff = (n & 127) * 32;
            const __nv_bfloat16 *pa, *pb;
            if (seg == 0)      { pa = g_Ah; pb = g_Kth; }
            else if (seg == 1) { pa = g_Al; pb = g_Kth; }
            else               { pa = g_Ah; pb = g_Ktl; }
            load_tile(sA[1 - b], pa, pBase, NREF, kOff, tid);
            load_tile(sB[1 - b], pb, jBase, NREF, kOff, tid);
            asm volatile("cp.async.commit_group;" ::: "memory");
            asm volatile("cp.async.wait_group 1;" ::: "memory");
        } else {
            asm volatile("cp.async.wait_group 0;" ::: "memory");
        }
        __syncthreads();
        compute_k32(sA[b], sB[b], warpM, warpN, lane, c);
        __syncthreads();
    }

#pragma unroll
    for (int mi = 0; mi < 2; mi++) {
        const int r0 = pBase + warpM * 32 + mi * 16 + (lane >> 2);
        const size_t ro0 = (size_t)r0 * NIN, ro1 = (size_t)(r0 + 8) * NIN;
#pragma unroll
        for (int ni = 0; ni < 8; ni++) {
            const int col = jBase + warpN * 64 + ni * 8 + 2 * (lane & 3);
            float2 v01 = make_float2(c[mi][ni][0], c[mi][ni][1]);
            float2 v23 = make_float2(c[mi][ni][2], c[mi][ni][3]);
            *(float2*)(Y + ro0 + col) = v01;
            *(float2*)(Y + ro1 + col) = v23;
        }
    }
}

// ---------------------------------------------------------------------------
// fp32 -> bf16 hi/lo splits
// ---------------------------------------------------------------------------
__device__ __forceinline__ void split2(float2 v, __nv_bfloat162* hp, __nv_bfloat162* lp, int i) {
    __nv_bfloat16 h0 = __float2bfloat16(v.x), h1 = __float2bfloat16(v.y);
    __nv_bfloat162 hh, ll;
    hh.x = h0; hh.y = h1;
    ll.x = __float2bfloat16(v.x - __bfloat162float(h0));
    ll.y = __float2bfloat16(v.y - __bfloat162float(h1));
    hp[i] = hh; lp[i] = ll;
}
__global__ void split_X(const float* __restrict__ x) {
    int i = blockIdx.x * blockDim.x + threadIdx.x;
    if (i < NREF * DFEAT / 2)
        split2(((const float2*)x)[i], (__nv_bfloat162*)g_Xh, (__nv_bfloat162*)g_Xl, i);
}
__global__ void split_D(const float* __restrict__ x) {
    int i = blockIdx.x * blockDim.x + threadIdx.x;
    if (i < NIN * DFEAT / 2)
        split2(((const float2*)x)[i], (__nv_bfloat162*)g_Dh, (__nv_bfloat162*)g_Dl, i);
}
__global__ void split_A(const float* __restrict__ x) {
    int i = blockIdx.x * blockDim.x + threadIdx.x;
    if (i < PDIM * NREF / 2)
        split2(((const float2*)x)[i], (__nv_bfloat162*)g_Ah, (__nv_bfloat162*)g_Al, i);
}

extern "C" void kernel_launch(void* const* d_in, const int* in_sizes, int n_in,
                              void* d_out, int out_size) {
    const float* Alpha = (const float*)d_in[0];
    const float* X_ref = (const float*)d_in[1];
    const float* desc  = (const float*)d_in[2];
    const int*   Z_ref = (const int*)d_in[3];
    const int*   Z     = (const int*)d_in[4];
    const int*   expK  = (const int*)d_in[5];
    float* Y = (float*)d_out;

    split_X<<<(NREF * DFEAT / 2 + 255) / 256, 256>>>(X_ref);
    split_D<<<(NIN * DFEAT / 2 + 255) / 256, 256>>>(desc);
    split_A<<<(PDIM * NREF / 2 + 255) / 256, 256>>>(Alpha);

    gemm1_mma<<<dim3(NREF / 128, NIN / 128), 256>>>(Z, Z_ref, expK);
    gemm2_mma<<<dim3(NIN / 128, PDIM / 128), 256>>>(Y);
}

// round 4
// speedup vs baseline: 2.4910x; 1.2888x over previous
#include <cuda_runtime.h>
#include <cuda_bf16.h>

#define NREF  4096
#define NIN   8192
#define DFEAT 512
#define PDIM  256
#define LDS   40          // 32 + 8 pad (bf16 elems) -> 80B row stride

#define TILE_ELEMS (128 * LDS)
#define TILE_BYTES (TILE_ELEMS * 2)       // 10240
#define STAGE_BYTES (4 * TILE_BYTES)      // 40960: Ah, Al, Bh, Bl
#define SMEM_TOTAL (2 * STAGE_BYTES + 512)

// ---------------- scratch (device globals: allocation-guard safe) ----------
__device__ __nv_bfloat16 g_Xh[NREF * DFEAT];
__device__ __nv_bfloat16 g_Xl[NREF * DFEAT];
__device__ __nv_bfloat16 g_Dh[NIN * DFEAT];
__device__ __nv_bfloat16 g_Dl[NIN * DFEAT];
__device__ __nv_bfloat16 g_Ah[PDIM * NREF];
__device__ __nv_bfloat16 g_Al[PDIM * NREF];
__device__ __nv_bfloat16 g_Kth[(size_t)NIN * NREF];   // K^T hi  [NIN, NREF]
__device__ __nv_bfloat16 g_Ktl[(size_t)NIN * NREF];   // K^T lo

__device__ __forceinline__ unsigned sm32(const void* p) {
    unsigned r;
    asm("{.reg .u64 t; cvta.to.shared.u64 t, %1; cvt.u32.u64 %0, t;}" : "=r"(r) : "l"(p));
    return r;
}

// Load one 128x32 bf16 tile (row-major source, row stride K elems) via cp.async.
__device__ __forceinline__ void load_tile(unsigned sbuf, const __nv_bfloat16* src,
                                          int rowBase, int K, int kOff, int tid) {
    const int row = tid >> 1;
    const char* g = (const char*)(src + (size_t)(rowBase + row) * K + kOff + (tid & 1) * 16);
    const unsigned s = sbuf + row * (LDS * 2) + (tid & 1) * 32;
    asm volatile("cp.async.cg.shared.global [%0], [%1], 16;\n\t"
                 "cp.async.cg.shared.global [%2], [%3], 16;"
                 :: "r"(s), "l"(g), "r"(s + 16), "l"(g + 16));
}

__device__ __forceinline__ void mma16(float* c, const unsigned* a, unsigned b0, unsigned b1) {
    asm volatile(
        "mma.sync.aligned.m16n8k16.row.col.f32.bf16.bf16.f32 "
        "{%0,%1,%2,%3}, {%4,%5,%6,%7}, {%8,%9}, {%0,%1,%2,%3};"
        : "+f"(c[0]), "+f"(c[1]), "+f"(c[2]), "+f"(c[3])
        : "r"(a[0]), "r"(a[1]), "r"(a[2]), "r"(a[3]), "r"(b0), "r"(b1));
}

#define LDSM4(r, addr)                                                           \
    asm volatile("ldmatrix.sync.aligned.m8n8.x4.shared.b16 {%0,%1,%2,%3}, [%4];" \
                 : "=r"((r)[0]), "=r"((r)[1]), "=r"((r)[2]), "=r"((r)[3])        \
                 : "r"(addr))

// One BLK_K=32 stage with fused 3-term split accumulation:
//   c += Ah.Bh + Ah.Bl + Al.Bh   (all into the same accumulators)
__device__ __forceinline__ void compute3_k32(unsigned sAh, unsigned sAl,
                                             unsigned sBh, unsigned sBl,
                                             int warpM, int warpN, int lane,
                                             float (*c)[8][4]) {
#pragma unroll
    for (int kk = 0; kk < 32; kk += 16) {
        const unsigned aoff = ((warpM * 32 + (lane & 15)) * LDS + kk + (lane >> 4) * 8) * 2;
        unsigned ah[2][4], al[2][4];
        LDSM4(ah[0], sAh + aoff);
        LDSM4(ah[1], sAh + aoff + 16 * LDS * 2);
        LDSM4(al[0], sAl + aoff);
        LDSM4(al[1], sAl + aoff + 16 * LDS * 2);
#pragma unroll
        for (int g = 0; g < 4; g++) {
            const unsigned boff = ((warpN * 64 + g * 16 + (lane & 7) + ((lane >> 4) & 1) * 8) * LDS
                                   + kk + ((lane >> 3) & 1) * 8) * 2;
            unsigned bh[4], bl[4];
            LDSM4(bh, sBh + boff);
            LDSM4(bl, sBl + boff);
#pragma unroll
            for (int mi = 0; mi < 2; mi++) {
                mma16(c[mi][2 * g],     ah[mi], bh[0], bh[1]);
                mma16(c[mi][2 * g + 1], ah[mi], bh[2], bh[3]);
                mma16(c[mi][2 * g],     ah[mi], bl[0], bl[1]);
                mma16(c[mi][2 * g + 1], ah[mi], bl[2], bl[3]);
                mma16(c[mi][2 * g],     al[mi], bh[0], bh[1]);
                mma16(c[mi][2 * g + 1], al[mi], bh[2], bh[3]);
            }
        }
    }
}

// ---------------------------------------------------------------------------
// GEMM1 (transposed): Kt[j,i] = mask(Z[j]==Z_ref[i]) * (desc[j].X_ref[i])^expK
// ---------------------------------------------------------------------------
__global__ __launch_bounds__(256, 2) void gemm1_mma(const int* __restrict__ Zq,
                                                    const int* __restrict__ Zx,
                                                    const int* __restrict__ expKp) {
    extern __shared__ char dynsm[];
    const int tid = threadIdx.x, lane = tid & 31, wid = tid >> 5;
    const int warpM = wid & 3, warpN = wid >> 2;
    const int jBase = blockIdx.y * 128, iBase = blockIdx.x * 128;

    int* Zcol = (int*)(dynsm + 2 * STAGE_BYTES);
    if (tid < 128) Zcol[tid] = Zx[iBase + tid];

    float c[2][8][4];
#pragma unroll
    for (int i = 0; i < 2; i++)
#pragma unroll
        for (int j = 0; j < 8; j++)
#pragma unroll
            for (int k = 0; k < 4; k++) c[i][j][k] = 0.0f;

    unsigned st[2][4];
#pragma unroll
    for (int s = 0; s < 2; s++)
#pragma unroll
        for (int t = 0; t < 4; t++)
            st[s][t] = sm32(dynsm + s * STAGE_BYTES + t * TILE_BYTES);

    // prologue: chunk 0 -> stage 0
    load_tile(st[0][0], g_Dh, jBase, DFEAT, 0, tid);
    load_tile(st[0][1], g_Dl, jBase, DFEAT, 0, tid);
    load_tile(st[0][2], g_Xh, iBase, DFEAT, 0, tid);
    load_tile(st[0][3], g_Xl, iBase, DFEAT, 0, tid);
    asm volatile("cp.async.commit_group;" ::: "memory");

    const int NITER = DFEAT / 32;       // 16
    for (int it = 0; it < NITER; it++) {
        const int b = it & 1;
        if (it + 1 < NITER) {
            const int kOff = (it + 1) * 32;
            load_tile(st[1 - b][0], g_Dh, jBase, DFEAT, kOff, tid);
            load_tile(st[1 - b][1], g_Dl, jBase, DFEAT, kOff, tid);
            load_tile(st[1 - b][2], g_Xh, iBase, DFEAT, kOff, tid);
            load_tile(st[1 - b][3], g_Xl, iBase, DFEAT, kOff, tid);
            asm volatile("cp.async.commit_group;" ::: "memory");
            asm volatile("cp.async.wait_group 1;" ::: "memory");
        } else {
            asm volatile("cp.async.wait_group 0;" ::: "memory");
        }
        __syncthreads();
        compute3_k32(st[b][0], st[b][1], st[b][2], st[b][3], warpM, warpN, lane, c);
        __syncthreads();
    }

    // epilogue: pow, mask, bf16 hi/lo split, store K^T
    const int e = expKp[0];
#pragma unroll
    for (int mi = 0; mi < 2; mi++) {
        const int r0 = jBase + warpM * 32 + mi * 16 + (lane >> 2);
        const int zr0 = Zq[r0], zr1 = Zq[r0 + 8];
        const size_t ro0 = (size_t)r0 * NREF, ro1 = (size_t)(r0 + 8) * NREF;
#pragma unroll
        for (int ni = 0; ni < 8; ni++) {
            const int colL = warpN * 64 + ni * 8 + 2 * (lane & 3);
            const int zc0 = Zcol[colL], zc1 = Zcol[colL + 1];
            float v0 = c[mi][ni][0], v1 = c[mi][ni][1];
            float v2 = c[mi][ni][2], v3 = c[mi][ni][3];
            float p0 = 1.f, p1 = 1.f, p2 = 1.f, p3 = 1.f;
            for (int t = 0; t < e; t++) { p0 *= v0; p1 *= v1; p2 *= v2; p3 *= v3; }
            if (zr0 != zc0) p0 = 0.f;
            if (zr0 != zc1) p1 = 0.f;
            if (zr1 != zc0) p2 = 0.f;
            if (zr1 != zc1) p3 = 0.f;

            __nv_bfloat16 h0 = __float2bfloat16(p0), h1 = __float2bfloat16(p1);
            __nv_bfloat16 h2 = __float2bfloat16(p2), h3 = __float2bfloat16(p3);
            __nv_bfloat162 hh01, hh23, ll01, ll23;
            hh01.x = h0; hh01.y = h1;
            hh23.x = h2; hh23.y = h3;
            ll01.x = __float2bfloat16(p0 - __bfloat162float(h0));
            ll01.y = __float2bfloat16(p1 - __bfloat162float(h1));
            ll23.x = __float2bfloat16(p2 - __bfloat162float(h2));
            ll23.y = __float2bfloat16(p3 - __bfloat162float(h3));

            const size_t cg = (size_t)iBase + colL;
            *(__nv_bfloat162*)(g_Kth + ro0 + cg) = hh01;
            *(__nv_bfloat162*)(g_Kth + ro1 + cg) = hh23;
            *(__nv_bfloat162*)(g_Ktl + ro0 + cg) = ll01;
            *(__nv_bfloat162*)(g_Ktl + ro1 + cg) = ll23;
        }
    }
}

// ---------------------------------------------------------------------------
// GEMM2: Y[p,j] = Alpha[p] . Kt[j]  (Ah.Kh + Ah.Kl + Al.Kh fused per chunk)
// ---------------------------------------------------------------------------
__global__ __launch_bounds__(256, 2) void gemm2_mma(float* __restrict__ Y) {
    extern __shared__ char dynsm[];
    const int tid = threadIdx.x, lane = tid & 31, wid = tid >> 5;
    const int warpM = wid & 3, warpN = wid >> 2;
    const int pBase = blockIdx.y * 128, jBase = blockIdx.x * 128;

    float c[2][8][4];
#pragma unroll
    for (int i = 0; i < 2; i++)
#pragma unroll
        for (int j = 0; j < 8; j++)
#pragma unroll
            for (int k = 0; k < 4; k++) c[i][j][k] = 0.0f;

    unsigned st[2][4];
#pragma unroll
    for (int s = 0; s < 2; s++)
#pragma unroll
        for (int t = 0; t < 4; t++)
            st[s][t] = sm32(dynsm + s * STAGE_BYTES + t * TILE_BYTES);

    load_tile(st[0][0], g_Ah, pBase, NREF, 0, tid);
    load_tile(st[0][1], g_Al, pBase, NREF, 0, tid);
    load_tile(st[0][2], g_Kth, jBase, NREF, 0, tid);
    load_tile(st[0][3], g_Ktl, jBase, NREF, 0, tid);
    asm volatile("cp.async.commit_group;" ::: "memory");

    const int NITER = NREF / 32;        // 128
    for (int it = 0; it < NITER; it++) {
        const int b = it & 1;
        if (it + 1 < NITER) {
            const int kOff = (it + 1) * 32;
            load_tile(st[1 - b][0], g_Ah, pBase, NREF, kOff, tid);
            load_tile(st[1 - b][1], g_Al, pBase, NREF, kOff, tid);
            load_tile(st[1 - b][2], g_Kth, jBase, NREF, kOff, tid);
            load_tile(st[1 - b][3], g_Ktl, jBase, NREF, kOff, tid);
            asm volatile("cp.async.commit_group;" ::: "memory");
            asm volatile("cp.async.wait_group 1;" ::: "memory");
        } else {
            asm volatile("cp.async.wait_group 0;" ::: "memory");
        }
        __syncthreads();
        compute3_k32(st[b][0], st[b][1], st[b][2], st[b][3], warpM, warpN, lane, c);
        __syncthreads();
    }

#pragma unroll
    for (int mi = 0; mi < 2; mi++) {
        const int r0 = pBase + warpM * 32 + mi * 16 + (lane >> 2);
        const size_t ro0 = (size_t)r0 * NIN, ro1 = (size_t)(r0 + 8) * NIN;
#pragma unroll
        for (int ni = 0; ni < 8; ni++) {
            const int col = jBase + warpN * 64 + ni * 8 + 2 * (lane & 3);
            *(float2*)(Y + ro0 + col) = make_float2(c[mi][ni][0], c[mi][ni][1]);
            *(float2*)(Y + ro1 + col) = make_float2(c[mi][ni][2], c[mi][ni][3]);
        }
    }
}

// ---------------------------------------------------------------------------
// fp32 -> bf16 hi/lo splits
// ---------------------------------------------------------------------------
__device__ __forceinline__ void split2(float2 v, __nv_bfloat162* hp, __nv_bfloat162* lp, int i) {
    __nv_bfloat16 h0 = __float2bfloat16(v.x), h1 = __float2bfloat16(v.y);
    __nv_bfloat162 hh, ll;
    hh.x = h0; hh.y = h1;
    ll.x = __float2bfloat16(v.x - __bfloat162float(h0));
    ll.y = __float2bfloat16(v.y - __bfloat162float(h1));
    hp[i] = hh; lp[i] = ll;
}
__global__ void split_X(const float* __restrict__ x) {
    int i = blockIdx.x * blockDim.x + threadIdx.x;
    if (i < NREF * DFEAT / 2)
        split2(((const float2*)x)[i], (__nv_bfloat162*)g_Xh, (__nv_bfloat162*)g_Xl, i);
}
__global__ void split_D(const float* __restrict__ x) {
    int i = blockIdx.x * blockDim.x + threadIdx.x;
    if (i < NIN * DFEAT / 2)
        split2(((const float2*)x)[i], (__nv_bfloat162*)g_Dh, (__nv_bfloat162*)g_Dl, i);
}
__global__ void split_A(const float* __restrict__ x) {
    int i = blockIdx.x * blockDim.x + threadIdx.x;
    if (i < PDIM * NREF / 2)
        split2(((const float2*)x)[i], (__nv_bfloat162*)g_Ah, (__nv_bfloat162*)g_Al, i);
}

extern "C" void kernel_launch(void* const* d_in, const int* in_sizes, int n_in,
                              void* d_out, int out_size) {
    const float* Alpha = (const float*)d_in[0];
    const float* X_ref = (const float*)d_in[1];
    const float* desc  = (const float*)d_in[2];
    const int*   Z_ref = (const int*)d_in[3];
    const int*   Z     = (const int*)d_in[4];
    const int*   expK  = (const int*)d_in[5];
    float* Y = (float*)d_out;

    cudaFuncSetAttribute(gemm1_mma, cudaFuncAttributeMaxDynamicSharedMemorySize, SMEM_TOTAL);
    cudaFuncSetAttribute(gemm2_mma, cudaFuncAttributeMaxDynamicSharedMemorySize, SMEM_TOTAL);

    split_X<<<(NREF * DFEAT / 2 + 255) / 256, 256>>>(X_ref);
    split_D<<<(NIN * DFEAT / 2 + 255) / 256, 256>>>(desc);
    split_A<<<(PDIM * NREF / 2 + 255) / 256, 256>>>(Alpha);

    gemm1_mma<<<dim3(NREF / 128, NIN / 128), 256, SMEM_TOTAL>>>(Z, Z_ref, expK);
    gemm2_mma<<<dim3(NIN / 128, PDIM / 128), 256, SMEM_TOTAL>>>(Y);
}